// round 1
// baseline (speedup 1.0000x reference)
#include <cuda_runtime.h>
#include <cstdint>

#define BB 8
#define CC 64
#define NN 4096
#define CI 8
#define HALF_N 2048
#define TN 512

// ---------------- scratch (no allocation allowed) ----------------
__device__ __align__(16) float g_q[BB * NN * CI];          // [b][n][8]
__device__ __align__(16) float g_k[BB * NN * CI];          // [b][m][8], pre-scaled by log2e/sqrt(8)
__device__ __align__(16) float g_v[BB * NN * CI];          // [b][n][8]
__device__ __align__(16) float g_S[2 * BB * NN];           // [half][b*N+m]
__device__ __align__(16) float g_A[2 * BB * NN * CI];      // [half][b*N+m][8]

// ---------------- f32x2 helpers ----------------
__device__ __forceinline__ unsigned long long pk2(float lo, float hi) {
    unsigned long long r;
    asm("mov.b64 %0, {%1,%2};" : "=l"(r) : "f"(lo), "f"(hi));
    return r;
}
__device__ __forceinline__ void up2(unsigned long long p, float& lo, float& hi) {
    asm("mov.b64 {%0,%1}, %2;" : "=f"(lo), "=f"(hi) : "l"(p));
}
__device__ __forceinline__ unsigned long long ffma2(unsigned long long a, unsigned long long b,
                                                    unsigned long long c) {
    unsigned long long d;
    asm("fma.rn.f32x2 %0, %1, %2, %3;" : "=l"(d) : "l"(a), "l"(b), "l"(c));
    return d;
}
__device__ __forceinline__ unsigned long long fmul2(unsigned long long a, unsigned long long b) {
    unsigned long long d;
    asm("mul.rn.f32x2 %0, %1, %2;" : "=l"(d) : "l"(a), "l"(b));
    return d;
}
__device__ __forceinline__ float ex2f(float x) {
    float r;
    asm("ex2.approx.f32 %0, %1;" : "=f"(r) : "f"(x));
    return r;
}

// ---------------- kernel 1: q/k/v projections ----------------
__global__ void __launch_bounds__(256) proj_kernel(const float* __restrict__ x,
                                                   const float* __restrict__ Wq,
                                                   const float* __restrict__ Wk,
                                                   const float* __restrict__ Wv) {
    __shared__ float swq[CI * CC], swk[CI * CC], swv[CI * CC];
    int tid = threadIdx.x;
    for (int i = tid; i < CI * CC; i += 256) {
        swq[i] = Wq[i];
        swk[i] = Wk[i];
        swv[i] = Wv[i];
    }
    __syncthreads();

    int gid = blockIdx.x * 256 + tid;          // 0 .. B*N-1
    int b = gid >> 12;
    int n = gid & (NN - 1);

    float q[CI], k[CI], v[CI];
#pragma unroll
    for (int i = 0; i < CI; i++) { q[i] = 0.f; k[i] = 0.f; v[i] = 0.f; }

    const float* xp = x + (size_t)b * CC * NN + n;
#pragma unroll 8
    for (int c = 0; c < CC; c++) {
        float xv = xp[(size_t)c * NN];
#pragma unroll
        for (int i = 0; i < CI; i++) {
            q[i] = fmaf(swq[i * CC + c], xv, q[i]);
            k[i] = fmaf(swk[i * CC + c], xv, k[i]);
            v[i] = fmaf(swv[i * CC + c], xv, v[i]);
        }
    }

    const float KS = 0.51006971f;  // log2(e) / sqrt(8): fold scale + ex2 conversion into k
    size_t base = ((size_t)b * NN + n) * CI;
#pragma unroll
    for (int i = 0; i < CI; i++) {
        g_q[base + i] = q[i];
        g_k[base + i] = k[i] * KS;
        g_v[base + i] = v[i];
    }
}

// ---------------- kernel 2: fused attention (no-max softmax, n-split) ----------------
// grid = 256: cta = (b<<5) | (mt<<1) | half ; 128 threads, 2 m-columns per thread.
__global__ void __launch_bounds__(128) attn_kernel() {
    __shared__ uint4 sq[TN * 2];   // q tile: TN rows x 8 floats (2 x uint4 per row)
    __shared__ uint4 sv[TN * 2];   // v tile

    int tid = threadIdx.x;
    int cta = blockIdx.x;
    int half = cta & 1;
    int mt = (cta >> 1) & 15;
    int b = cta >> 5;

    int m0 = mt * 256 + tid;       // second column is m0 + 128
    size_t kb0 = ((size_t)b * NN + m0) * CI;
    size_t kb1 = ((size_t)b * NN + m0 + 128) * CI;

    const float4* kp0 = reinterpret_cast<const float4*>(&g_k[kb0]);
    const float4* kp1 = reinterpret_cast<const float4*>(&g_k[kb1]);
    float4 ka0 = kp0[0], kc0 = kp0[1];
    float4 ka1 = kp1[0], kc1 = kp1[1];

    unsigned long long k0[4] = {pk2(ka0.x, ka0.y), pk2(ka0.z, ka0.w),
                                pk2(kc0.x, kc0.y), pk2(kc0.z, kc0.w)};
    unsigned long long k1[4] = {pk2(ka1.x, ka1.y), pk2(ka1.z, ka1.w),
                                pk2(kc1.x, kc1.y), pk2(kc1.z, kc1.w)};

    unsigned long long A0[4] = {0ull, 0ull, 0ull, 0ull};
    unsigned long long A1[4] = {0ull, 0ull, 0ull, 0ull};
    float S0 = 0.f, S1 = 0.f;

    int nbase = half * HALF_N;

    for (int t = 0; t < HALF_N; t += TN) {
        const uint4* gq = reinterpret_cast<const uint4*>(&g_q[((size_t)b * NN + nbase + t) * CI]);
        const uint4* gv = reinterpret_cast<const uint4*>(&g_v[((size_t)b * NN + nbase + t) * CI]);
        __syncthreads();  // previous tile fully consumed
#pragma unroll
        for (int i = 0; i < (TN * 2) / 128; i++) {
            sq[i * 128 + tid] = gq[i * 128 + tid];
            sv[i * 128 + tid] = gv[i * 128 + tid];
        }
        __syncthreads();

        const ulonglong2* q2 = reinterpret_cast<const ulonglong2*>(sq);
        const ulonglong2* v2 = reinterpret_cast<const ulonglong2*>(sv);

#pragma unroll 4
        for (int j = 0; j < TN; j++) {
            ulonglong2 qa = q2[j * 2];       // q01, q23
            ulonglong2 qb = q2[j * 2 + 1];   // q45, q67
            ulonglong2 va = v2[j * 2];
            ulonglong2 vb = v2[j * 2 + 1];

            // column m0
            {
                unsigned long long d = fmul2(qa.x, k0[0]);
                d = ffma2(qa.y, k0[1], d);
                d = ffma2(qb.x, k0[2], d);
                d = ffma2(qb.y, k0[3], d);
                float lo, hi;
                up2(d, lo, hi);
                float e = ex2f(lo + hi);     // scale folded into k
                S0 += e;
                unsigned long long ee = pk2(e, e);
                A0[0] = ffma2(ee, va.x, A0[0]);
                A0[1] = ffma2(ee, va.y, A0[1]);
                A0[2] = ffma2(ee, vb.x, A0[2]);
                A0[3] = ffma2(ee, vb.y, A0[3]);
            }
            // column m1 = m0 + 128
            {
                unsigned long long d = fmul2(qa.x, k1[0]);
                d = ffma2(qa.y, k1[1], d);
                d = ffma2(qb.x, k1[2], d);
                d = ffma2(qb.y, k1[3], d);
                float lo, hi;
                up2(d, lo, hi);
                float e = ex2f(lo + hi);
                S1 += e;
                unsigned long long ee = pk2(e, e);
                A1[0] = ffma2(ee, va.x, A1[0]);
                A1[1] = ffma2(ee, va.y, A1[1]);
                A1[2] = ffma2(ee, vb.x, A1[2]);
                A1[3] = ffma2(ee, vb.y, A1[3]);
            }
        }
    }

    size_t i0 = (size_t)half * (BB * NN) + (size_t)b * NN + m0;
    g_S[i0] = S0;
    g_S[i0 + 128] = S1;
    {
        float* a = &g_A[i0 * CI];
        float l, h;
        up2(A0[0], l, h); a[0] = l; a[1] = h;
        up2(A0[1], l, h); a[2] = l; a[3] = h;
        up2(A0[2], l, h); a[4] = l; a[5] = h;
        up2(A0[3], l, h); a[6] = l; a[7] = h;
    }
    {
        float* a = &g_A[(i0 + 128) * CI];
        float l, h;
        up2(A1[0], l, h); a[0] = l; a[1] = h;
        up2(A1[1], l, h); a[2] = l; a[3] = h;
        up2(A1[2], l, h); a[4] = l; a[5] = h;
        up2(A1[3], l, h); a[6] = l; a[7] = h;
    }
}

// ---------------- kernel 3: combine halves, normalize, Wout GEMV, residual ----------------
__global__ void __launch_bounds__(256) epi_kernel(const float* __restrict__ x,
                                                  const float* __restrict__ Wout,
                                                  float* __restrict__ out) {
    __shared__ float sw[CC * CI];
    int tid = threadIdx.x;
    for (int i = tid; i < CC * CI; i += 256) sw[i] = Wout[i];
    __syncthreads();

    int gid = blockIdx.x * 256 + tid;  // 0 .. B*N-1
    int b = gid >> 12;
    int m = gid & (NN - 1);

    float S = g_S[gid] + g_S[BB * NN + gid];
    float inv = 1.0f / S;

    float att[CI];
    const float* a0 = &g_A[(size_t)gid * CI];
    const float* a1 = &g_A[((size_t)(BB * NN) + gid) * CI];
#pragma unroll
    for (int i = 0; i < CI; i++) att[i] = (a0[i] + a1[i]) * inv;

    const float* xp = x + (size_t)b * CC * NN + m;
    float* op = out + (size_t)b * CC * NN + m;
#pragma unroll 8
    for (int c = 0; c < CC; c++) {
        float o = 0.f;
#pragma unroll
        for (int i = 0; i < CI; i++) o = fmaf(sw[c * CI + i], att[i], o);
        op[(size_t)c * NN] = fmaf(0.1f, o, xp[(size_t)c * NN]);
    }
}

// ---------------- launch ----------------
extern "C" void kernel_launch(void* const* d_in, const int* in_sizes, int n_in,
                              void* d_out, int out_size) {
    const float* x = (const float*)d_in[0];
    const float* Wq = (const float*)d_in[1];
    const float* Wk = (const float*)d_in[2];
    const float* Wv = (const float*)d_in[3];
    const float* Wout = (const float*)d_in[4];
    float* out = (float*)d_out;

    proj_kernel<<<(BB * NN) / 256, 256>>>(x, Wq, Wk, Wv);
    attn_kernel<<<256, 128>>>();
    epi_kernel<<<(BB * NN) / 256, 256>>>(x, Wout, out);
}

// round 3
// speedup vs baseline: 3.2574x; 3.2574x over previous
#include <cuda_runtime.h>
#include <cuda_fp16.h>
#include <cstdint>

#define BB 8
#define CC 64
#define NN 4096
#define CI 8

// ---------------- f16 intermediates (scratch; no allocation allowed) -------
__device__ __align__(16) __half g_qh[BB * NN * CI];   // [b][n][8]
__device__ __align__(16) __half g_kh[BB * NN * CI];   // [b][m][8], pre-scaled log2e/sqrt(8)
__device__ __align__(16) __half g_vt[BB * CI * NN];   // [b][i][n]  (V transposed)

// ---------------- mma helpers (baseline sm_80+ features only) --------------
__device__ __forceinline__ void mma_m16n8k8(float& d0, float& d1, float& d2, float& d3,
                                            uint32_t a0, uint32_t a1, uint32_t b0) {
    asm("mma.sync.aligned.m16n8k8.row.col.f32.f16.f16.f32 "
        "{%0,%1,%2,%3}, {%4,%5}, {%6}, {%7,%8,%9,%10};"
        : "=f"(d0), "=f"(d1), "=f"(d2), "=f"(d3)
        : "r"(a0), "r"(a1), "r"(b0), "f"(0.f), "f"(0.f), "f"(0.f), "f"(0.f));
}
__device__ __forceinline__ void mma_m16n8k16(float& c0, float& c1, float& c2, float& c3,
                                             uint32_t a0, uint32_t a1, uint32_t a2, uint32_t a3,
                                             uint32_t b0, uint32_t b1) {
    asm("mma.sync.aligned.m16n8k16.row.col.f32.f16.f16.f32 "
        "{%0,%1,%2,%3}, {%4,%5,%6,%7}, {%8,%9}, {%0,%1,%2,%3};"
        : "+f"(c0), "+f"(c1), "+f"(c2), "+f"(c3)
        : "r"(a0), "r"(a1), "r"(a2), "r"(a3), "r"(b0), "r"(b1));
}
__device__ __forceinline__ uint32_t ex2_h2(uint32_t x) {
    uint32_t r;
    asm("ex2.approx.f16x2 %0, %1;" : "=r"(r) : "r"(x));
    return r;
}
__device__ __forceinline__ uint32_t pack_h2(float lo, float hi) {
    __half2 h = __floats2half2_rn(lo, hi);
    return *reinterpret_cast<uint32_t*>(&h);
}

// ---------------- kernel 1: q/k/v projections (2-way c-split) --------------
__global__ void __launch_bounds__(256) proj_kernel(const float* __restrict__ x,
                                                   const float* __restrict__ Wq,
                                                   const float* __restrict__ Wk,
                                                   const float* __restrict__ Wv) {
    __shared__ float swq[CI * CC], swk[CI * CC], swv[CI * CC];
    int tid = threadIdx.x;
    for (int i = tid; i < CI * CC; i += 256) {
        swq[i] = Wq[i]; swk[i] = Wk[i]; swv[i] = Wv[i];
    }
    __syncthreads();

    int wid = tid >> 5, lane = tid & 31;
    int half = lane >> 4, nl = lane & 15;
    int slot = blockIdx.x * 128 + wid * 16 + nl;   // 256 blocks -> 32768 slots
    int b = slot >> 12, n = slot & (NN - 1);

    float q[CI], k[CI], v[CI];
#pragma unroll
    for (int i = 0; i < CI; i++) { q[i] = 0.f; k[i] = 0.f; v[i] = 0.f; }

    const float* xp = x + (size_t)b * CC * NN + n;
    int c0 = half * 32;
#pragma unroll 8
    for (int j = 0; j < 32; j++) {
        int c = c0 + j;
        float xv = xp[(size_t)c * NN];
#pragma unroll
        for (int i = 0; i < CI; i++) {
            q[i] = fmaf(swq[i * CC + c], xv, q[i]);
            k[i] = fmaf(swk[i * CC + c], xv, k[i]);
            v[i] = fmaf(swv[i * CC + c], xv, v[i]);
        }
    }
#pragma unroll
    for (int i = 0; i < CI; i++) {
        q[i] += __shfl_xor_sync(0xffffffffu, q[i], 16);
        k[i] += __shfl_xor_sync(0xffffffffu, k[i], 16);
        v[i] += __shfl_xor_sync(0xffffffffu, v[i], 16);
    }
    if (half == 0) {
        const float KS = 0.51006971f;  // log2(e)/sqrt(8)
        size_t base = ((size_t)b * NN + n) * CI;
        __half2 qh[4], kh[4];
#pragma unroll
        for (int i = 0; i < 4; i++) {
            qh[i] = __floats2half2_rn(q[2 * i], q[2 * i + 1]);
            kh[i] = __floats2half2_rn(k[2 * i] * KS, k[2 * i + 1] * KS);
        }
        *reinterpret_cast<uint4*>(&g_qh[base]) = *reinterpret_cast<uint4*>(qh);
        *reinterpret_cast<uint4*>(&g_kh[base]) = *reinterpret_cast<uint4*>(kh);
        __half* vt = g_vt + (size_t)b * CI * NN + n;
#pragma unroll
        for (int i = 0; i < CI; i++) vt[(size_t)i * NN] = __float2half_rn(v[i]);
    }
}

// ---------------- kernel 2: FA2-style fused attention + epilogue -----------
// grid 512: b = bx>>6, mtile = bx&63 (64 m-rows per CTA). 128 threads = 4 warps,
// warp w owns m rows [m0 + 16w, m0 + 16w + 16).
#define VPAD 264   // padded halves per Vt smem row (bank-conflict-free)

__global__ void __launch_bounds__(128) attn_kernel(const float* __restrict__ x,
                                                   const float* __restrict__ Wout,
                                                   float* __restrict__ out) {
    __shared__ __align__(16) uint4 sQ[256];            // Q tile [256][8] halves
    __shared__ __align__(16) __half sV[CI * VPAD];     // Vt tile [8][256] padded
    __shared__ float sAtt[64 * 9];                     // att [64][8] padded stride 9
    __shared__ float sW[CC * CI];

    int tid = threadIdx.x, wid = tid >> 5, lane = tid & 31;
    int gid = lane >> 2, cp = lane & 3;
    int b = blockIdx.x >> 6, mt = blockIdx.x & 63;
    int m0 = mt * 64;

    for (int i = tid; i < CC * CI; i += 128) sW[i] = Wout[i];

    // K fragment (fixed for whole kernel): rows m0+16w+gid, m0+16w+gid+8
    int mrow = m0 + wid * 16 + gid;
    uint32_t ka0 = *reinterpret_cast<const uint32_t*>(
        &g_kh[((size_t)b * NN + mrow) * CI + 2 * cp]);
    uint32_t ka1 = *reinterpret_cast<const uint32_t*>(
        &g_kh[((size_t)b * NN + mrow + 8) * CI + 2 * cp]);

    const uint4* qbase = reinterpret_cast<const uint4*>(g_qh + (size_t)b * NN * CI);
    const __half* vbase = g_vt + (size_t)b * CI * NN;

    float acc0 = 0.f, acc1 = 0.f, acc2 = 0.f, acc3 = 0.f;
    float dr0 = 0.f, dr1 = 0.f;

    // preload n-block 0
    uint4 q4a = qbase[tid];
    uint4 q4b = qbase[tid + 128];
    int r0 = tid >> 5, c0i = tid & 31;
    int r1 = (tid + 128) >> 5, c1i = tid & 31;
    uint4 v4a = *reinterpret_cast<const uint4*>(vbase + (size_t)r0 * NN + c0i * 8);
    uint4 v4b = *reinterpret_cast<const uint4*>(vbase + (size_t)r1 * NN + c1i * 8);

    const uint32_t* sQw = reinterpret_cast<const uint32_t*>(sQ);

    for (int bi = 0; bi < 16; bi++) {
        sQ[tid] = q4a;
        sQ[tid + 128] = q4b;
        *reinterpret_cast<uint4*>(&sV[r0 * VPAD + c0i * 8]) = v4a;
        *reinterpret_cast<uint4*>(&sV[r1 * VPAD + c1i * 8]) = v4b;
        __syncthreads();

        if (bi < 15) {
            int n1 = (bi + 1) * 256;
            q4a = qbase[n1 + tid];
            q4b = qbase[n1 + tid + 128];
            v4a = *reinterpret_cast<const uint4*>(vbase + (size_t)r0 * NN + n1 + c0i * 8);
            v4b = *reinterpret_cast<const uint4*>(vbase + (size_t)r1 * NN + n1 + c1i * 8);
        }

#pragma unroll 4
        for (int ck = 0; ck < 16; ck++) {
            int no = ck * 16;
            uint32_t qlo = sQw[(no + gid) * 4 + cp];
            uint32_t qhi = sQw[(no + 8 + gid) * 4 + cp];

            float d0, d1, d2, d3, e0, e1, e2, e3;
            mma_m16n8k8(d0, d1, d2, d3, ka0, ka1, qlo);
            mma_m16n8k8(e0, e1, e2, e3, ka0, ka1, qhi);

            uint32_t p01 = ex2_h2(pack_h2(d0, d1));   // row gid,   cols no+2cp..
            uint32_t p23 = ex2_h2(pack_h2(d2, d3));   // row gid+8
            uint32_t p45 = ex2_h2(pack_h2(e0, e1));   // row gid,   cols no+8+2cp..
            uint32_t p67 = ex2_h2(pack_h2(e2, e3));   // row gid+8

            // denominators (f32-accurate)
            __half2 ha = __hadd2(*reinterpret_cast<__half2*>(&p01),
                                 *reinterpret_cast<__half2*>(&p45));
            __half2 hb = __hadd2(*reinterpret_cast<__half2*>(&p23),
                                 *reinterpret_cast<__half2*>(&p67));
            float2 fa = __half22float2(ha), fb = __half22float2(hb);
            dr0 += fa.x + fa.y;
            dr1 += fb.x + fb.y;

            uint32_t vb0 = *reinterpret_cast<const uint32_t*>(&sV[gid * VPAD + no + 2 * cp]);
            uint32_t vb1 = *reinterpret_cast<const uint32_t*>(&sV[gid * VPAD + no + 8 + 2 * cp]);
            mma_m16n8k16(acc0, acc1, acc2, acc3, p01, p23, p45, p67, vb0, vb1);
        }
        __syncthreads();
    }

    // reduce denominators across the 4 threads sharing each row
    dr0 += __shfl_xor_sync(0xffffffffu, dr0, 1);
    dr0 += __shfl_xor_sync(0xffffffffu, dr0, 2);
    dr1 += __shfl_xor_sync(0xffffffffu, dr1, 1);
    dr1 += __shfl_xor_sync(0xffffffffu, dr1, 2);
    float inv0 = 1.0f / dr0, inv1 = 1.0f / dr1;

    int rl = wid * 16 + gid;
    sAtt[rl * 9 + 2 * cp] = acc0 * inv0;
    sAtt[rl * 9 + 2 * cp + 1] = acc1 * inv0;
    sAtt[(rl + 8) * 9 + 2 * cp] = acc2 * inv1;
    sAtt[(rl + 8) * 9 + 2 * cp + 1] = acc3 * inv1;
    __syncthreads();

    // epilogue: out = x + 0.1 * Wout @ att ; thread -> (m_local, 32 c's)
    int ml = tid & 63, chalf = tid >> 6;
    float att[CI];
#pragma unroll
    for (int i = 0; i < CI; i++) att[i] = sAtt[ml * 9 + i];

    int m = m0 + ml;
    const float* xp = x + (size_t)b * CC * NN + m;
    float* op = out + (size_t)b * CC * NN + m;
#pragma unroll 8
    for (int j = 0; j < 32; j++) {
        int c = chalf * 32 + j;
        float o = 0.f;
#pragma unroll
        for (int i = 0; i < CI; i++) o = fmaf(sW[c * CI + i], att[i], o);
        op[(size_t)c * NN] = fmaf(0.1f, o, xp[(size_t)c * NN]);
    }
}

// ---------------- launch ----------------
extern "C" void kernel_launch(void* const* d_in, const int* in_sizes, int n_in,
                              void* d_out, int out_size) {
    const float* x = (const float*)d_in[0];
    const float* Wq = (const float*)d_in[1];
    const float* Wk = (const float*)d_in[2];
    const float* Wv = (const float*)d_in[3];
    const float* Wout = (const float*)d_in[4];
    float* out = (float*)d_out;

    proj_kernel<<<256, 256>>>(x, Wq, Wk, Wv);
    attn_kernel<<<512, 128>>>(x, Wout, out);
}

// round 4
// speedup vs baseline: 3.4368x; 1.0551x over previous
#include <cuda_runtime.h>
#include <cuda_fp16.h>
#include <cstdint>

#define BB 8
#define CC 64
#define NN 4096
#define CI 8

// ---------------- scratch (no allocation allowed) ----------------
__device__ __align__(16) __half g_qh[BB * NN * CI];   // [b][n][8]
__device__ __align__(16) __half g_kh[BB * NN * CI];   // [b][m][8], pre-scaled log2e/sqrt(8)
__device__ __align__(16) __half g_vt[BB * CI * NN];   // [b][i][n]  (V transposed)
__device__ __align__(16) float  g_pA[2 * BB * NN * CI]; // [half][b][m][8] partial P@V
__device__ __align__(16) float  g_pD[2 * BB * NN];      // [half][b][m]    partial denom
__device__ int g_cnt[BB * 64];                          // split-K arrival counters (self-reset)

// ---------------- mma helpers (baseline sm_80+ features only) --------------
__device__ __forceinline__ void mma_m16n8k8(float& d0, float& d1, float& d2, float& d3,
                                            uint32_t a0, uint32_t a1, uint32_t b0) {
    asm("mma.sync.aligned.m16n8k8.row.col.f32.f16.f16.f32 "
        "{%0,%1,%2,%3}, {%4,%5}, {%6}, {%7,%8,%9,%10};"
        : "=f"(d0), "=f"(d1), "=f"(d2), "=f"(d3)
        : "r"(a0), "r"(a1), "r"(b0), "f"(0.f), "f"(0.f), "f"(0.f), "f"(0.f));
}
__device__ __forceinline__ void mma_m16n8k16(float& c0, float& c1, float& c2, float& c3,
                                             uint32_t a0, uint32_t a1, uint32_t a2, uint32_t a3,
                                             uint32_t b0, uint32_t b1) {
    asm("mma.sync.aligned.m16n8k16.row.col.f32.f16.f16.f32 "
        "{%0,%1,%2,%3}, {%4,%5,%6,%7}, {%8,%9}, {%0,%1,%2,%3};"
        : "+f"(c0), "+f"(c1), "+f"(c2), "+f"(c3)
        : "r"(a0), "r"(a1), "r"(a2), "r"(a3), "r"(b0), "r"(b1));
}
__device__ __forceinline__ uint32_t ex2_h2(uint32_t x) {
    uint32_t r;
    asm("ex2.approx.f16x2 %0, %1;" : "=r"(r) : "r"(x));
    return r;
}
__device__ __forceinline__ uint32_t pack_h2(float lo, float hi) {
    __half2 h = __floats2half2_rn(lo, hi);
    return *reinterpret_cast<uint32_t*>(&h);
}

// ---------------- kernel 1: q/k/v projections (4-way c-split) --------------
__global__ void __launch_bounds__(256) proj_kernel(const float* __restrict__ x,
                                                   const float* __restrict__ Wq,
                                                   const float* __restrict__ Wk,
                                                   const float* __restrict__ Wv) {
    __shared__ float swq[CI * CC], swk[CI * CC], swv[CI * CC];
    __shared__ __half sv[CI][64];
    int tid = threadIdx.x;
    for (int i = tid; i < CI * CC; i += 256) {
        swq[i] = Wq[i]; swk[i] = Wk[i]; swv[i] = Wv[i];
    }
    __syncthreads();

    int wid = tid >> 5, lane = tid & 31;
    int quarter = lane >> 3, nl = lane & 7;
    int slot = blockIdx.x * 64 + wid * 8 + nl;     // grid 512 -> 32768 slots
    int b = slot >> 12, n = slot & (NN - 1);
    int nloc = (wid << 3) | nl;                    // 0..63 within CTA

    float q[CI], k[CI], v[CI];
#pragma unroll
    for (int i = 0; i < CI; i++) { q[i] = 0.f; k[i] = 0.f; v[i] = 0.f; }

    const float* xp = x + (size_t)b * CC * NN + n;
    int c0 = quarter * 16;
#pragma unroll
    for (int j = 0; j < 16; j++) {
        int c = c0 + j;
        float xv = xp[(size_t)c * NN];
#pragma unroll
        for (int i = 0; i < CI; i++) {
            q[i] = fmaf(swq[i * CC + c], xv, q[i]);
            k[i] = fmaf(swk[i * CC + c], xv, k[i]);
            v[i] = fmaf(swv[i * CC + c], xv, v[i]);
        }
    }
#pragma unroll
    for (int i = 0; i < CI; i++) {
        q[i] += __shfl_xor_sync(0xffffffffu, q[i], 8);
        k[i] += __shfl_xor_sync(0xffffffffu, k[i], 8);
        v[i] += __shfl_xor_sync(0xffffffffu, v[i], 8);
        q[i] += __shfl_xor_sync(0xffffffffu, q[i], 16);
        k[i] += __shfl_xor_sync(0xffffffffu, k[i], 16);
        v[i] += __shfl_xor_sync(0xffffffffu, v[i], 16);
    }
    if (quarter == 0) {
        const float KS = 0.51006971f;  // log2(e)/sqrt(8)
        size_t base = ((size_t)b * NN + n) * CI;
        __half2 qh[4], kh[4];
#pragma unroll
        for (int i = 0; i < 4; i++) {
            qh[i] = __floats2half2_rn(q[2 * i], q[2 * i + 1]);
            kh[i] = __floats2half2_rn(k[2 * i] * KS, k[2 * i + 1] * KS);
        }
        *reinterpret_cast<uint4*>(&g_qh[base]) = *reinterpret_cast<uint4*>(qh);
        *reinterpret_cast<uint4*>(&g_kh[base]) = *reinterpret_cast<uint4*>(kh);
#pragma unroll
        for (int i = 0; i < CI; i++) sv[i][nloc] = __float2half_rn(v[i]);
    }
    __syncthreads();
    // coalesced transposed V store: 64 threads, one uint4 (8 halves) each
    if (tid < 64) {
        int row = tid >> 3, chunk = tid & 7;
        int nbase = (blockIdx.x & 63) * 64;        // CTA's n range within batch b
        int bb = blockIdx.x >> 6;
        *reinterpret_cast<uint4*>(g_vt + ((size_t)bb * CI + row) * NN + nbase + chunk * 8) =
            *reinterpret_cast<const uint4*>(&sv[row][chunk * 8]);
    }
}

// ---------------- kernel 2: FA2 attention, split-K over n + fused epilogue --
// grid 1024: b = bx>>7, mt = (bx>>1)&63, half = bx&1. 128 threads = 4 warps,
// warp w owns m rows [m0+16w, m0+16w+16), n range = [half*2048, half*2048+2048).
#define VPAD 264

__global__ void __launch_bounds__(128) attn_kernel(const float* __restrict__ x,
                                                   const float* __restrict__ Wout,
                                                   float* __restrict__ out) {
    __shared__ __align__(16) uint4 sQ[256];          // Q tile [256][8] halves
    __shared__ __align__(16) __half sV[CI * VPAD];   // Vt tile [8][256] padded
    __shared__ float sAtt[64 * 9];
    __shared__ float sW[CC * CI];
    __shared__ int s_old;

    int tid = threadIdx.x, wid = tid >> 5, lane = tid & 31;
    int gid = lane >> 2, cp = lane & 3;
    int b = blockIdx.x >> 7, mt = (blockIdx.x >> 1) & 63, half = blockIdx.x & 1;
    int m0 = mt * 64;
    int nbase = half * 2048;

    // K fragment (fixed): rows m0+16w+gid, +8
    int mrow = m0 + wid * 16 + gid;
    uint32_t ka0 = *reinterpret_cast<const uint32_t*>(
        &g_kh[((size_t)b * NN + mrow) * CI + 2 * cp]);
    uint32_t ka1 = *reinterpret_cast<const uint32_t*>(
        &g_kh[((size_t)b * NN + mrow + 8) * CI + 2 * cp]);

    const uint4* qbase = reinterpret_cast<const uint4*>(g_qh + (size_t)b * NN * CI);
    const __half* vbase = g_vt + (size_t)b * CI * NN;

    float acc0 = 0.f, acc1 = 0.f, acc2 = 0.f, acc3 = 0.f;
    float den0 = 0.f, den1 = 0.f, den2 = 0.f, den3 = 0.f;
    const uint32_t ONES = 0x3C003C00u;   // half2(1,1)

    int r0 = tid >> 5, c0i = tid & 31;
    int r1 = (tid + 128) >> 5;

    uint4 q4a = qbase[nbase + tid];
    uint4 q4b = qbase[nbase + tid + 128];
    uint4 v4a = *reinterpret_cast<const uint4*>(vbase + (size_t)r0 * NN + nbase + c0i * 8);
    uint4 v4b = *reinterpret_cast<const uint4*>(vbase + (size_t)r1 * NN + nbase + c0i * 8);

    const uint32_t* sQw = reinterpret_cast<const uint32_t*>(sQ);

    for (int bi = 0; bi < 8; bi++) {
        sQ[tid] = q4a;
        sQ[tid + 128] = q4b;
        *reinterpret_cast<uint4*>(&sV[r0 * VPAD + c0i * 8]) = v4a;
        *reinterpret_cast<uint4*>(&sV[r1 * VPAD + c0i * 8]) = v4b;
        __syncthreads();

        if (bi < 7) {
            int n1 = nbase + (bi + 1) * 256;
            q4a = qbase[n1 + tid];
            q4b = qbase[n1 + tid + 128];
            v4a = *reinterpret_cast<const uint4*>(vbase + (size_t)r0 * NN + n1 + c0i * 8);
            v4b = *reinterpret_cast<const uint4*>(vbase + (size_t)r1 * NN + n1 + c0i * 8);
        }

#pragma unroll 4
        for (int ck = 0; ck < 16; ck++) {
            int no = ck * 16;
            uint32_t qlo = sQw[(no + gid) * 4 + cp];
            uint32_t qhi = sQw[(no + 8 + gid) * 4 + cp];

            float d0, d1, d2, d3, e0, e1, e2, e3;
            mma_m16n8k8(d0, d1, d2, d3, ka0, ka1, qlo);
            mma_m16n8k8(e0, e1, e2, e3, ka0, ka1, qhi);

            uint32_t p01 = ex2_h2(pack_h2(d0, d1));
            uint32_t p23 = ex2_h2(pack_h2(d2, d3));
            uint32_t p45 = ex2_h2(pack_h2(e0, e1));
            uint32_t p67 = ex2_h2(pack_h2(e2, e3));

            uint32_t vb0 = *reinterpret_cast<const uint32_t*>(&sV[gid * VPAD + no + 2 * cp]);
            uint32_t vb1 = *reinterpret_cast<const uint32_t*>(&sV[gid * VPAD + no + 8 + 2 * cp]);
            mma_m16n8k16(acc0, acc1, acc2, acc3, p01, p23, p45, p67, vb0, vb1);
            mma_m16n8k16(den0, den1, den2, den3, p01, p23, p45, p67, ONES, ONES);
        }
        __syncthreads();
    }

    // write partials: rows mrow, mrow+8; cols 2cp, 2cp+1
    {
        size_t rb = ((size_t)half * BB + b) * NN;
        *reinterpret_cast<float2*>(&g_pA[(rb + mrow) * CI + 2 * cp]) = make_float2(acc0, acc1);
        *reinterpret_cast<float2*>(&g_pA[(rb + mrow + 8) * CI + 2 * cp]) = make_float2(acc2, acc3);
        if (cp == 0) {
            g_pD[rb + mrow] = den0;      // all cols of den are equal (rowsum)
            g_pD[rb + mrow + 8] = den2;
        }
    }
    __threadfence();
    __syncthreads();
    if (tid == 0) s_old = atomicAdd(&g_cnt[b * 64 + mt], 1);
    __syncthreads();
    if (s_old == 0) return;              // winner exits; loser merges + epilogue
    if (tid == 0) g_cnt[b * 64 + mt] = 0;  // reset for next (graph-replayed) launch
    __threadfence();

    for (int i = tid; i < CC * CI; i += 128) sW[i] = Wout[i];
    if (tid < 64) {
        int m = m0 + tid;
        const float4* a0 = reinterpret_cast<const float4*>(&g_pA[((size_t)b * NN + m) * CI]);
        const float4* a1 = reinterpret_cast<const float4*>(&g_pA[((size_t)(BB + b) * NN + m) * CI]);
        float den = g_pD[(size_t)b * NN + m] + g_pD[(size_t)(BB + b) * NN + m];
        float inv = 1.0f / den;
        float4 x0 = a0[0], x1 = a0[1], y0 = a1[0], y1 = a1[1];
        sAtt[tid * 9 + 0] = (x0.x + y0.x) * inv;
        sAtt[tid * 9 + 1] = (x0.y + y0.y) * inv;
        sAtt[tid * 9 + 2] = (x0.z + y0.z) * inv;
        sAtt[tid * 9 + 3] = (x0.w + y0.w) * inv;
        sAtt[tid * 9 + 4] = (x1.x + y1.x) * inv;
        sAtt[tid * 9 + 5] = (x1.y + y1.y) * inv;
        sAtt[tid * 9 + 6] = (x1.z + y1.z) * inv;
        sAtt[tid * 9 + 7] = (x1.w + y1.w) * inv;
    }
    __syncthreads();

    // epilogue: out = x + 0.1 * Wout @ att
    int ml = tid & 63, chalf = tid >> 6;
    float att[CI];
#pragma unroll
    for (int i = 0; i < CI; i++) att[i] = sAtt[ml * 9 + i];

    int m = m0 + ml;
    const float* xp = x + (size_t)b * CC * NN + m;
    float* op = out + (size_t)b * CC * NN + m;
#pragma unroll 8
    for (int j = 0; j < 32; j++) {
        int c = chalf * 32 + j;
        float o = 0.f;
#pragma unroll
        for (int i = 0; i < CI; i++) o = fmaf(sW[c * CI + i], att[i], o);
        op[(size_t)c * NN] = fmaf(0.1f, o, xp[(size_t)c * NN]);
    }
}

// ---------------- launch ----------------
extern "C" void kernel_launch(void* const* d_in, const int* in_sizes, int n_in,
                              void* d_out, int out_size) {
    const float* x = (const float*)d_in[0];
    const float* Wq = (const float*)d_in[1];
    const float* Wk = (const float*)d_in[2];
    const float* Wv = (const float*)d_in[3];
    const float* Wout = (const float*)d_in[4];
    float* out = (float*)d_out;

    proj_kernel<<<512, 256>>>(x, Wq, Wk, Wv);
    attn_kernel<<<1024, 128>>>(x, Wout, out);
}

// round 5
// speedup vs baseline: 3.5726x; 1.0395x over previous
#include <cuda_runtime.h>
#include <cuda_fp16.h>
#include <cstdint>

#define BB 8
#define CC 64
#define NN 4096
#define CI 8

// ---------------- scratch (no allocation allowed) ----------------
__device__ __align__(16) __half g_qh[BB * NN * CI];     // [b][n][8]
__device__ __align__(16) __half g_kh[BB * NN * CI];     // [b][m][8], pre-scaled log2e/sqrt(8)
__device__ __align__(16) __half g_vt[BB * CI * NN];     // [b][i][n]  (V transposed)
__device__ __align__(16) float  g_pA[4 * BB * NN * CI]; // [q][b][m][8] partial P@V
__device__ __align__(16) float  g_pD[4 * BB * NN];      // [q][b][m]   partial denom
__device__ int g_cnt[BB * 64];                          // split-K arrival counters (self-reset)

// ---------------- mma helpers (baseline sm_80+ features only) --------------
__device__ __forceinline__ void mma_m16n8k8(float& d0, float& d1, float& d2, float& d3,
                                            uint32_t a0, uint32_t a1, uint32_t b0) {
    asm("mma.sync.aligned.m16n8k8.row.col.f32.f16.f16.f32 "
        "{%0,%1,%2,%3}, {%4,%5}, {%6}, {%7,%8,%9,%10};"
        : "=f"(d0), "=f"(d1), "=f"(d2), "=f"(d3)
        : "r"(a0), "r"(a1), "r"(b0), "f"(0.f), "f"(0.f), "f"(0.f), "f"(0.f));
}
__device__ __forceinline__ void mma_m16n8k16(float& c0, float& c1, float& c2, float& c3,
                                             uint32_t a0, uint32_t a1, uint32_t a2, uint32_t a3,
                                             uint32_t b0, uint32_t b1) {
    asm("mma.sync.aligned.m16n8k16.row.col.f32.f16.f16.f32 "
        "{%0,%1,%2,%3}, {%4,%5,%6,%7}, {%8,%9}, {%0,%1,%2,%3};"
        : "+f"(c0), "+f"(c1), "+f"(c2), "+f"(c3)
        : "r"(a0), "r"(a1), "r"(a2), "r"(a3), "r"(b0), "r"(b1));
}
__device__ __forceinline__ uint32_t ex2_h2(uint32_t x) {
    uint32_t r;
    asm("ex2.approx.f16x2 %0, %1;" : "=r"(r) : "r"(x));
    return r;
}
__device__ __forceinline__ uint32_t pack_h2(float lo, float hi) {
    __half2 h = __floats2half2_rn(lo, hi);
    return *reinterpret_cast<uint32_t*>(&h);
}

// ---------------- kernel 1: q/k/v projections (4-way c-split) --------------
__global__ void __launch_bounds__(256) proj_kernel(const float* __restrict__ x,
                                                   const float* __restrict__ Wq,
                                                   const float* __restrict__ Wk,
                                                   const float* __restrict__ Wv) {
    __shared__ float swq[CI * CC], swk[CI * CC], swv[CI * CC];
    __shared__ __half sv[CI][64];
    int tid = threadIdx.x;
    for (int i = tid; i < CI * CC; i += 256) {
        swq[i] = Wq[i]; swk[i] = Wk[i]; swv[i] = Wv[i];
    }
    __syncthreads();

    int wid = tid >> 5, lane = tid & 31;
    int quarter = lane >> 3, nl = lane & 7;
    int slot = blockIdx.x * 64 + wid * 8 + nl;     // grid 512 -> 32768 slots
    int b = slot >> 12, n = slot & (NN - 1);
    int nloc = (wid << 3) | nl;

    float q[CI], k[CI], v[CI];
#pragma unroll
    for (int i = 0; i < CI; i++) { q[i] = 0.f; k[i] = 0.f; v[i] = 0.f; }

    const float* xp = x + (size_t)b * CC * NN + n;
    int c0 = quarter * 16;
#pragma unroll
    for (int j = 0; j < 16; j++) {
        int c = c0 + j;
        float xv = xp[(size_t)c * NN];
#pragma unroll
        for (int i = 0; i < CI; i++) {
            q[i] = fmaf(swq[i * CC + c], xv, q[i]);
            k[i] = fmaf(swk[i * CC + c], xv, k[i]);
            v[i] = fmaf(swv[i * CC + c], xv, v[i]);
        }
    }
#pragma unroll
    for (int i = 0; i < CI; i++) {
        q[i] += __shfl_xor_sync(0xffffffffu, q[i], 8);
        k[i] += __shfl_xor_sync(0xffffffffu, k[i], 8);
        v[i] += __shfl_xor_sync(0xffffffffu, v[i], 8);
        q[i] += __shfl_xor_sync(0xffffffffu, q[i], 16);
        k[i] += __shfl_xor_sync(0xffffffffu, k[i], 16);
        v[i] += __shfl_xor_sync(0xffffffffu, v[i], 16);
    }
    if (quarter == 0) {
        const float KS = 0.51006971f;  // log2(e)/sqrt(8)
        size_t base = ((size_t)b * NN + n) * CI;
        __half2 qh[4], kh[4];
#pragma unroll
        for (int i = 0; i < 4; i++) {
            qh[i] = __floats2half2_rn(q[2 * i], q[2 * i + 1]);
            kh[i] = __floats2half2_rn(k[2 * i] * KS, k[2 * i + 1] * KS);
        }
        *reinterpret_cast<uint4*>(&g_qh[base]) = *reinterpret_cast<uint4*>(qh);
        *reinterpret_cast<uint4*>(&g_kh[base]) = *reinterpret_cast<uint4*>(kh);
#pragma unroll
        for (int i = 0; i < CI; i++) sv[i][nloc] = __float2half_rn(v[i]);
    }
    __syncthreads();
    if (tid < 64) {
        int row = tid >> 3, chunk = tid & 7;
        int nbase = (blockIdx.x & 63) * 64;
        int bb = blockIdx.x >> 6;
        *reinterpret_cast<uint4*>(g_vt + ((size_t)bb * CI + row) * NN + nbase + chunk * 8) =
            *reinterpret_cast<const uint4*>(&sv[row][chunk * 8]);
    }
}

// ---------------- kernel 2: FA2 attention, split-K(4) + chunk-pair ILP ------
// grid 2048: b = bx>>8, mt = (bx>>2)&63, quarter = bx&3. 128 threads = 4 warps,
// warp w owns m rows [m0+16w, m0+16w+16), n range = quarter*1024 .. +1024.
#define VPAD 264

__global__ void __launch_bounds__(128) attn_kernel(const float* __restrict__ x,
                                                   const float* __restrict__ Wout,
                                                   float* __restrict__ out) {
    __shared__ __align__(16) uint4 sQ[256];          // Q tile [256][8] halves
    __shared__ __align__(16) __half sV[CI * VPAD];   // Vt tile [8][256] padded
    __shared__ float sAtt[64 * 9];
    __shared__ float sW[CC * CI];
    __shared__ int s_old;

    int tid = threadIdx.x, wid = tid >> 5, lane = tid & 31;
    int gid = lane >> 2, cp = lane & 3;
    int b = blockIdx.x >> 8, mt = (blockIdx.x >> 2) & 63, quarter = blockIdx.x & 3;
    int m0 = mt * 64;
    int nbase = quarter * 1024;

    int mrow = m0 + wid * 16 + gid;
    uint32_t ka0 = *reinterpret_cast<const uint32_t*>(
        &g_kh[((size_t)b * NN + mrow) * CI + 2 * cp]);
    uint32_t ka1 = *reinterpret_cast<const uint32_t*>(
        &g_kh[((size_t)b * NN + mrow + 8) * CI + 2 * cp]);

    const uint4* qbase = reinterpret_cast<const uint4*>(g_qh + (size_t)b * NN * CI);
    const __half* vbase = g_vt + (size_t)b * CI * NN;

    // two independent accumulator sets (even / odd chunks)
    float aE0 = 0.f, aE1 = 0.f, aE2 = 0.f, aE3 = 0.f;
    float aO0 = 0.f, aO1 = 0.f, aO2 = 0.f, aO3 = 0.f;
    float dE0 = 0.f, dE1 = 0.f, dE2 = 0.f, dE3 = 0.f;
    float dO0 = 0.f, dO1 = 0.f, dO2 = 0.f, dO3 = 0.f;
    const uint32_t ONES = 0x3C003C00u;

    int r0 = tid >> 5, c0i = tid & 31;
    int r1 = (tid + 128) >> 5;

    uint4 q4a = qbase[nbase + tid];
    uint4 q4b = qbase[nbase + tid + 128];
    uint4 v4a = *reinterpret_cast<const uint4*>(vbase + (size_t)r0 * NN + nbase + c0i * 8);
    uint4 v4b = *reinterpret_cast<const uint4*>(vbase + (size_t)r1 * NN + nbase + c0i * 8);

    const uint32_t* sQw = reinterpret_cast<const uint32_t*>(sQ);
    const uint32_t* qp = sQw + gid * 4 + cp;                 // row stride 4 u32
    const __half* vp = sV + gid * VPAD + 2 * cp;

    for (int bi = 0; bi < 4; bi++) {
        sQ[tid] = q4a;
        sQ[tid + 128] = q4b;
        *reinterpret_cast<uint4*>(&sV[r0 * VPAD + c0i * 8]) = v4a;
        *reinterpret_cast<uint4*>(&sV[r1 * VPAD + c0i * 8]) = v4b;
        __syncthreads();

        if (bi < 3) {
            int n1 = nbase + (bi + 1) * 256;
            q4a = qbase[n1 + tid];
            q4b = qbase[n1 + tid + 128];
            v4a = *reinterpret_cast<const uint4*>(vbase + (size_t)r0 * NN + n1 + c0i * 8);
            v4b = *reinterpret_cast<const uint4*>(vbase + (size_t)r1 * NN + n1 + c0i * 8);
        }

#pragma unroll
        for (int ckp = 0; ckp < 8; ckp++) {
            int no = ckp * 32;          // even chunk cols no..no+15, odd no+16..no+31
            // S phase, both chunks (independent chains)
            uint32_t qeL = qp[(no) * 4], qeH = qp[(no + 8) * 4];
            uint32_t qoL = qp[(no + 16) * 4], qoH = qp[(no + 24) * 4];

            float e0, e1, e2, e3, f0, f1, f2, f3;
            float g0, g1, g2, g3, h0, h1, h2, h3;
            mma_m16n8k8(e0, e1, e2, e3, ka0, ka1, qeL);
            mma_m16n8k8(f0, f1, f2, f3, ka0, ka1, qeH);
            mma_m16n8k8(g0, g1, g2, g3, ka0, ka1, qoL);
            mma_m16n8k8(h0, h1, h2, h3, ka0, ka1, qoH);

            uint32_t pe01 = ex2_h2(pack_h2(e0, e1));
            uint32_t pe23 = ex2_h2(pack_h2(e2, e3));
            uint32_t pe45 = ex2_h2(pack_h2(f0, f1));
            uint32_t pe67 = ex2_h2(pack_h2(f2, f3));
            uint32_t po01 = ex2_h2(pack_h2(g0, g1));
            uint32_t po23 = ex2_h2(pack_h2(g2, g3));
            uint32_t po45 = ex2_h2(pack_h2(h0, h1));
            uint32_t po67 = ex2_h2(pack_h2(h2, h3));

            uint32_t vbe0 = *reinterpret_cast<const uint32_t*>(vp + no);
            uint32_t vbe1 = *reinterpret_cast<const uint32_t*>(vp + no + 8);
            uint32_t vbo0 = *reinterpret_cast<const uint32_t*>(vp + no + 16);
            uint32_t vbo1 = *reinterpret_cast<const uint32_t*>(vp + no + 24);

            // PV phase: two independent accumulator chains
            mma_m16n8k16(aE0, aE1, aE2, aE3, pe01, pe23, pe45, pe67, vbe0, vbe1);
            mma_m16n8k16(aO0, aO1, aO2, aO3, po01, po23, po45, po67, vbo0, vbo1);
            mma_m16n8k16(dE0, dE1, dE2, dE3, pe01, pe23, pe45, pe67, ONES, ONES);
            mma_m16n8k16(dO0, dO1, dO2, dO3, po01, po23, po45, po67, ONES, ONES);
        }
        __syncthreads();
    }

    float acc0 = aE0 + aO0, acc1 = aE1 + aO1, acc2 = aE2 + aO2, acc3 = aE3 + aO3;
    float den0 = dE0 + dO0, den2 = dE2 + dO2;

    {
        size_t rb = ((size_t)quarter * BB + b) * NN;
        *reinterpret_cast<float2*>(&g_pA[(rb + mrow) * CI + 2 * cp]) = make_float2(acc0, acc1);
        *reinterpret_cast<float2*>(&g_pA[(rb + mrow + 8) * CI + 2 * cp]) = make_float2(acc2, acc3);
        if (cp == 0) {
            g_pD[rb + mrow] = den0;
            g_pD[rb + mrow + 8] = den2;
        }
    }
    __threadfence();
    __syncthreads();
    if (tid == 0) s_old = atomicAdd(&g_cnt[b * 64 + mt], 1);
    __syncthreads();
    if (s_old != 3) return;                // first three exit; last merges + epilogue
    if (tid == 0) g_cnt[b * 64 + mt] = 0;  // reset for next (graph-replayed) launch
    __threadfence();

    for (int i = tid; i < CC * CI; i += 128) sW[i] = Wout[i];
    if (tid < 64) {
        int m = m0 + tid;
        float acc[CI] = {0, 0, 0, 0, 0, 0, 0, 0};
        float den = 0.f;
#pragma unroll
        for (int qq = 0; qq < 4; qq++) {
            size_t rb = ((size_t)qq * BB + b) * NN + m;
            const float4* a = reinterpret_cast<const float4*>(&g_pA[rb * CI]);
            float4 x0 = a[0], x1 = a[1];
            acc[0] += x0.x; acc[1] += x0.y; acc[2] += x0.z; acc[3] += x0.w;
            acc[4] += x1.x; acc[5] += x1.y; acc[6] += x1.z; acc[7] += x1.w;
            den += g_pD[rb];
        }
        float inv = 1.0f / den;
#pragma unroll
        for (int i = 0; i < CI; i++) sAtt[tid * 9 + i] = acc[i] * inv;
    }
    __syncthreads();

    // epilogue: out = x + 0.1 * Wout @ att
    int ml = tid & 63, chalf = tid >> 6;
    float att[CI];
#pragma unroll
    for (int i = 0; i < CI; i++) att[i] = sAtt[ml * 9 + i];

    int m = m0 + ml;
    const float* xp = x + (size_t)b * CC * NN + m;
    float* op = out + (size_t)b * CC * NN + m;
#pragma unroll 8
    for (int j = 0; j < 32; j++) {
        int c = chalf * 32 + j;
        float o = 0.f;
#pragma unroll
        for (int i = 0; i < CI; i++) o = fmaf(sW[c * CI + i], att[i], o);
        op[(size_t)c * NN] = fmaf(0.1f, o, xp[(size_t)c * NN]);
    }
}

// ---------------- launch ----------------
extern "C" void kernel_launch(void* const* d_in, const int* in_sizes, int n_in,
                              void* d_out, int out_size) {
    const float* x = (const float*)d_in[0];
    const float* Wq = (const float*)d_in[1];
    const float* Wk = (const float*)d_in[2];
    const float* Wv = (const float*)d_in[3];
    const float* Wout = (const float*)d_in[4];
    float* out = (float*)d_out;

    proj_kernel<<<512, 256>>>(x, Wq, Wk, Wv);
    attn_kernel<<<2048, 128>>>(x, Wout, out);
}